// round 1
// baseline (speedup 1.0000x reference)
#include <cuda_runtime.h>
#include <cuda_fp16.h>
#include <cstdint>

// ---------------------------------------------------------------------------
// GroupedQueryAttention: q/k/v proj -> GQA flash attention -> out proj
// B=2, S=2048, IN=2048, DIMS=2048, QH=32, KH=8, HD=64, KV_DIM=512
// fp16 tensor-core (mma.sync m16n8k16) with fp32 accumulation throughout.
// ---------------------------------------------------------------------------

#define BB 2
#define SS 2048
#define IN_DIM 2048
#define DIMS 2048
#define QH 32
#define KH 8
#define HD 64
#define KV_DIM 512
#define MROWS (BB * SS)          // 4096
#define SM_SCALE 0.125f          // 1/sqrt(64)

// fp16 scratch (static device globals — no allocation)
__device__ __half g_Q[(size_t)MROWS * DIMS];
__device__ __half g_K[(size_t)MROWS * KV_DIM];
__device__ __half g_V[(size_t)MROWS * KV_DIM];
__device__ __half g_A[(size_t)MROWS * DIMS];

// ---------------------------------------------------------------------------

__device__ __forceinline__ void mma16816(float* c, const uint32_t* a, const uint32_t* b) {
    asm volatile(
        "mma.sync.aligned.m16n8k16.row.col.f32.f16.f16.f32 "
        "{%0,%1,%2,%3}, {%4,%5,%6,%7}, {%8,%9}, {%0,%1,%2,%3};\n"
        : "+f"(c[0]), "+f"(c[1]), "+f"(c[2]), "+f"(c[3])
        : "r"(a[0]), "r"(a[1]), "r"(a[2]), "r"(a[3]), "r"(b[0]), "r"(b[1]));
}

__device__ __forceinline__ uint32_t pack_h2(float x, float y) {
    __half2 h = __floats2half2_rn(x, y);
    return *reinterpret_cast<uint32_t*>(&h);
}

__device__ __forceinline__ __half to_h(float x) { return __float2half(x); }
__device__ __forceinline__ __half to_h(__half x) { return x; }

__device__ __forceinline__ void store_out(__half* p, float v0, float v1) {
    *reinterpret_cast<__half2*>(p) = __floats2half2_rn(v0, v1);
}
__device__ __forceinline__ void store_out(float* p, float v0, float v1) {
    *reinterpret_cast<float2*>(p) = make_float2(v0, v1);
}

// ---------------------------------------------------------------------------
// GEMM: C[M,N] = A[M,K] @ W[K,N] + bias.  Block tile 128x128x32, 256 thr.
// A converted to fp16 in smem; W converted to fp16, stored n-major (Bs[n][k]).
// ---------------------------------------------------------------------------
template <typename AT, typename OT>
__global__ __launch_bounds__(256)
void gemm_kernel(const AT* __restrict__ A, const float* __restrict__ W,
                 const float* __restrict__ bias, OT* __restrict__ C,
                 int M, int N, int K) {
    __shared__ __half As[128][34];
    __shared__ __half Bs[128][34];   // [n][k]

    const int tid  = threadIdx.x;
    const int warp = tid >> 5, lane = tid & 31;
    const int g = lane >> 2, t = lane & 3;
    const int bm = blockIdx.y * 128, bn = blockIdx.x * 128;
    const int wm = (warp >> 1) * 32, wn = (warp & 1) * 64;

    float acc[2][8][4];
#pragma unroll
    for (int a = 0; a < 2; a++)
#pragma unroll
        for (int b = 0; b < 8; b++)
#pragma unroll
            for (int c = 0; c < 4; c++) acc[a][b][c] = 0.f;

    for (int k0 = 0; k0 < K; k0 += 32) {
#pragma unroll
        for (int i = 0; i < 16; i++) {
            int idx = tid + i * 256;
            int r = idx >> 5, ck = idx & 31;
            As[r][ck] = to_h(A[(size_t)(bm + r) * K + k0 + ck]);
        }
#pragma unroll
        for (int i = 0; i < 16; i++) {
            int idx = tid + i * 256;
            int r = idx >> 7, cn = idx & 127;
            Bs[cn][r] = __float2half(W[(size_t)(k0 + r) * N + bn + cn]);
        }
        __syncthreads();

#pragma unroll
        for (int ks = 0; ks < 2; ks++) {
            const int kb = ks * 16;
            uint32_t af[2][4], bf[8][2];
#pragma unroll
            for (int mi = 0; mi < 2; mi++) {
                int r = wm + mi * 16 + g;
                af[mi][0] = *(const uint32_t*)&As[r][kb + t * 2];
                af[mi][1] = *(const uint32_t*)&As[r + 8][kb + t * 2];
                af[mi][2] = *(const uint32_t*)&As[r][kb + 8 + t * 2];
                af[mi][3] = *(const uint32_t*)&As[r + 8][kb + 8 + t * 2];
            }
#pragma unroll
            for (int ni = 0; ni < 8; ni++) {
                int cc = wn + ni * 8 + g;
                bf[ni][0] = *(const uint32_t*)&Bs[cc][kb + t * 2];
                bf[ni][1] = *(const uint32_t*)&Bs[cc][kb + 8 + t * 2];
            }
#pragma unroll
            for (int mi = 0; mi < 2; mi++)
#pragma unroll
                for (int ni = 0; ni < 8; ni++)
                    mma16816(acc[mi][ni], af[mi], bf[ni]);
        }
        __syncthreads();
    }

#pragma unroll
    for (int mi = 0; mi < 2; mi++) {
        int r0 = bm + wm + mi * 16 + g;
#pragma unroll
        for (int ni = 0; ni < 8; ni++) {
            int cc = bn + wn + ni * 8 + t * 2;
            float b0 = bias[cc], b1 = bias[cc + 1];
            store_out(&C[(size_t)r0 * N + cc], acc[mi][ni][0] + b0, acc[mi][ni][1] + b1);
            store_out(&C[(size_t)(r0 + 8) * N + cc], acc[mi][ni][2] + b0, acc[mi][ni][3] + b1);
        }
    }
}

// ---------------------------------------------------------------------------
// Flash attention (non-causal, full). Block = one (b, h, 64-row q tile).
// 4 warps x 16 rows. KV tiles of 64 keys, 32 iterations. Online softmax.
// ---------------------------------------------------------------------------
__global__ __launch_bounds__(128)
void attn_kernel(const __half* __restrict__ Qp, const __half* __restrict__ Kp,
                 const __half* __restrict__ Vp, __half* __restrict__ Op) {
    const int b = blockIdx.z, h = blockIdx.y, qt = blockIdx.x;
    const int kh = h >> 2;
    const int tid = threadIdx.x;
    const int warp = tid >> 5, lane = tid & 31;
    const int g = lane >> 2, t = lane & 3;

    __shared__ __half Qs[64][66];
    __shared__ __half Ks[64][66];
    __shared__ __half Vt[64][66];   // [d][key]

    // ---- load Q tile (64 x 64) ----
    const __half* qbase = Qp + ((size_t)(b * SS + qt * 64)) * DIMS + h * HD;
    for (int i = tid; i < 64 * 32; i += 128) {
        int r = i >> 5, d2 = i & 31;
        *(__half2*)&Qs[r][d2 * 2] = *(const __half2*)&qbase[(size_t)r * DIMS + d2 * 2];
    }
    __syncthreads();

    // Q fragments, register-resident for whole KV loop
    uint32_t qf[4][4];
    {
        int r = warp * 16 + g;
#pragma unroll
        for (int kk = 0; kk < 4; kk++) {
            qf[kk][0] = *(const uint32_t*)&Qs[r][kk * 16 + t * 2];
            qf[kk][1] = *(const uint32_t*)&Qs[r + 8][kk * 16 + t * 2];
            qf[kk][2] = *(const uint32_t*)&Qs[r][kk * 16 + 8 + t * 2];
            qf[kk][3] = *(const uint32_t*)&Qs[r + 8][kk * 16 + 8 + t * 2];
        }
    }

    float o[8][4];
#pragma unroll
    for (int j = 0; j < 8; j++)
#pragma unroll
        for (int p = 0; p < 4; p++) o[j][p] = 0.f;
    float m0 = -1e30f, m1 = -1e30f, l0 = 0.f, l1 = 0.f;

    const __half* kbase = Kp + ((size_t)b * SS) * KV_DIM + kh * HD;
    const __half* vbase = Vp + ((size_t)b * SS) * KV_DIM + kh * HD;

    for (int kt = 0; kt < 32; kt++) {
        __syncthreads();   // previous iter's reads complete before overwrite
        for (int i = tid; i < 64 * 32; i += 128) {
            int s = i >> 5, d2 = i & 31;
            *(__half2*)&Ks[s][d2 * 2] =
                *(const __half2*)&kbase[(size_t)(kt * 64 + s) * KV_DIM + d2 * 2];
            __half2 vv = *(const __half2*)&vbase[(size_t)(kt * 64 + s) * KV_DIM + d2 * 2];
            Vt[d2 * 2][s]     = __low2half(vv);
            Vt[d2 * 2 + 1][s] = __high2half(vv);
        }
        __syncthreads();

        // ---- scores: S = Q @ K^T (16 x 64 per warp) ----
        float sc[8][4];
#pragma unroll
        for (int j = 0; j < 8; j++)
#pragma unroll
            for (int p = 0; p < 4; p++) sc[j][p] = 0.f;

#pragma unroll
        for (int kk = 0; kk < 4; kk++)
#pragma unroll
            for (int j = 0; j < 8; j++) {
                uint32_t kf[2];
                kf[0] = *(const uint32_t*)&Ks[j * 8 + g][kk * 16 + t * 2];
                kf[1] = *(const uint32_t*)&Ks[j * 8 + g][kk * 16 + 8 + t * 2];
                mma16816(sc[j], qf[kk], kf);
            }

        // ---- online softmax (rows g and g+8 of this warp's 16) ----
        float mx0 = -1e30f, mx1 = -1e30f;
#pragma unroll
        for (int j = 0; j < 8; j++) {
            mx0 = fmaxf(mx0, fmaxf(sc[j][0], sc[j][1]));
            mx1 = fmaxf(mx1, fmaxf(sc[j][2], sc[j][3]));
        }
        mx0 = fmaxf(mx0, __shfl_xor_sync(0xffffffffu, mx0, 1));
        mx0 = fmaxf(mx0, __shfl_xor_sync(0xffffffffu, mx0, 2));
        mx1 = fmaxf(mx1, __shfl_xor_sync(0xffffffffu, mx1, 1));
        mx1 = fmaxf(mx1, __shfl_xor_sync(0xffffffffu, mx1, 2));

        float nm0 = fmaxf(m0, mx0 * SM_SCALE);
        float nm1 = fmaxf(m1, mx1 * SM_SCALE);
        float f0 = __expf(m0 - nm0), f1 = __expf(m1 - nm1);
        m0 = nm0; m1 = nm1;

        float rs0 = 0.f, rs1 = 0.f;
#pragma unroll
        for (int j = 0; j < 8; j++) {
            sc[j][0] = __expf(sc[j][0] * SM_SCALE - nm0); rs0 += sc[j][0];
            sc[j][1] = __expf(sc[j][1] * SM_SCALE - nm0); rs0 += sc[j][1];
            sc[j][2] = __expf(sc[j][2] * SM_SCALE - nm1); rs1 += sc[j][2];
            sc[j][3] = __expf(sc[j][3] * SM_SCALE - nm1); rs1 += sc[j][3];
        }
        l0 = l0 * f0 + rs0;
        l1 = l1 * f1 + rs1;
#pragma unroll
        for (int j = 0; j < 8; j++) {
            o[j][0] *= f0; o[j][1] *= f0;
            o[j][2] *= f1; o[j][3] *= f1;
        }

        // ---- O += P @ V ----
#pragma unroll
        for (int t2 = 0; t2 < 4; t2++) {
            uint32_t pf[4];
            pf[0] = pack_h2(sc[2 * t2][0],     sc[2 * t2][1]);
            pf[1] = pack_h2(sc[2 * t2][2],     sc[2 * t2][3]);
            pf[2] = pack_h2(sc[2 * t2 + 1][0], sc[2 * t2 + 1][1]);
            pf[3] = pack_h2(sc[2 * t2 + 1][2], sc[2 * t2 + 1][3]);
#pragma unroll
            for (int j = 0; j < 8; j++) {
                uint32_t vf[2];
                vf[0] = *(const uint32_t*)&Vt[j * 8 + g][t2 * 16 + t * 2];
                vf[1] = *(const uint32_t*)&Vt[j * 8 + g][t2 * 16 + 8 + t * 2];
                mma16816(o[j], pf, vf);
            }
        }
    }

    // ---- finalize ----
    l0 += __shfl_xor_sync(0xffffffffu, l0, 1);
    l0 += __shfl_xor_sync(0xffffffffu, l0, 2);
    l1 += __shfl_xor_sync(0xffffffffu, l1, 1);
    l1 += __shfl_xor_sync(0xffffffffu, l1, 2);
    float inv0 = 1.f / l0, inv1 = 1.f / l1;

    int q0 = qt * 64 + warp * 16 + g;
#pragma unroll
    for (int j = 0; j < 8; j++) {
        int cc = h * HD + j * 8 + t * 2;
        *(__half2*)&Op[(size_t)(b * SS + q0) * DIMS + cc] =
            __floats2half2_rn(o[j][0] * inv0, o[j][1] * inv0);
        *(__half2*)&Op[(size_t)(b * SS + q0 + 8) * DIMS + cc] =
            __floats2half2_rn(o[j][2] * inv1, o[j][3] * inv1);
    }
}

// ---------------------------------------------------------------------------

extern "C" void kernel_launch(void* const* d_in, const int* in_sizes, int n_in,
                              void* d_out, int out_size) {
    const float* q  = (const float*)d_in[0];
    const float* k  = (const float*)d_in[1];
    const float* v  = (const float*)d_in[2];
    const float* Wq = (const float*)d_in[3];
    const float* bq = (const float*)d_in[4];
    const float* Wk = (const float*)d_in[5];
    const float* bk = (const float*)d_in[6];
    const float* Wv = (const float*)d_in[7];
    const float* bv = (const float*)d_in[8];
    const float* Wo = (const float*)d_in[9];
    const float* bo = (const float*)d_in[10];
    float* out = (float*)d_out;

    __half *gq, *gk, *gv, *ga;
    cudaGetSymbolAddress((void**)&gq, g_Q);
    cudaGetSymbolAddress((void**)&gk, g_K);
    cudaGetSymbolAddress((void**)&gv, g_V);
    cudaGetSymbolAddress((void**)&ga, g_A);

    gemm_kernel<float, __half><<<dim3(DIMS / 128, MROWS / 128), 256>>>(
        q, Wq, bq, gq, MROWS, DIMS, IN_DIM);
    gemm_kernel<float, __half><<<dim3(KV_DIM / 128, MROWS / 128), 256>>>(
        k, Wk, bk, gk, MROWS, KV_DIM, IN_DIM);
    gemm_kernel<float, __half><<<dim3(KV_DIM / 128, MROWS / 128), 256>>>(
        v, Wv, bv, gv, MROWS, KV_DIM, IN_DIM);

    attn_kernel<<<dim3(SS / 64, QH, BB), 128>>>(gq, gk, gv, ga);

    gemm_kernel<__half, float><<<dim3(DIMS / 128, MROWS / 128), 256>>>(
        ga, Wo, bo, out, MROWS, DIMS, IN_DIM);
}

// round 3
// speedup vs baseline: 2.8177x; 2.8177x over previous
#include <cuda_runtime.h>
#include <cuda_fp16.h>
#include <cstdint>

// ---------------------------------------------------------------------------
// GQA: q/k/v proj -> flash attention -> out proj.  fp16 HMMA, fp32 accum.
// B=2, S=2048, IN=2048, DIMS=2048, QH=32, KH=8, HD=64, KV_DIM=512
// ---------------------------------------------------------------------------

#define BB 2
#define SS 2048
#define IN_DIM 2048
#define DIMS 2048
#define QH 32
#define KH 8
#define HD 64
#define KV_DIM 512
#define MROWS (BB * SS)          // 4096
#define SM_SCALE 0.125f

// fp16 scratch (static device globals — no allocation)
__device__ __half g_q16[(size_t)MROWS * IN_DIM];
__device__ __half g_k16[(size_t)MROWS * IN_DIM];
__device__ __half g_v16[(size_t)MROWS * IN_DIM];
__device__ __half g_Wq16[(size_t)IN_DIM * DIMS];
__device__ __half g_Wk16[(size_t)IN_DIM * KV_DIM];
__device__ __half g_Wv16[(size_t)IN_DIM * KV_DIM];
__device__ __half g_Wo16[(size_t)DIMS * IN_DIM];
__device__ __half g_Q[(size_t)MROWS * DIMS];
__device__ __half g_K[(size_t)MROWS * KV_DIM];
__device__ __half g_V[(size_t)MROWS * KV_DIM];
__device__ __half g_A[(size_t)MROWS * DIMS];

// ---------------------------------------------------------------------------

__device__ __forceinline__ void mma16816(float* c, const uint32_t* a, const uint32_t* b) {
    asm volatile(
        "mma.sync.aligned.m16n8k16.row.col.f32.f16.f16.f32 "
        "{%0,%1,%2,%3}, {%4,%5,%6,%7}, {%8,%9}, {%0,%1,%2,%3};\n"
        : "+f"(c[0]), "+f"(c[1]), "+f"(c[2]), "+f"(c[3])
        : "r"(a[0]), "r"(a[1]), "r"(a[2]), "r"(a[3]), "r"(b[0]), "r"(b[1]));
}

__device__ __forceinline__ uint32_t sptr(const void* p) {
    return (uint32_t)__cvta_generic_to_shared(p);
}

__device__ __forceinline__ void ldm_x4(uint32_t* r, uint32_t addr) {
    asm volatile("ldmatrix.sync.aligned.m8n8.x4.shared.b16 {%0,%1,%2,%3}, [%4];\n"
                 : "=r"(r[0]), "=r"(r[1]), "=r"(r[2]), "=r"(r[3]) : "r"(addr));
}
__device__ __forceinline__ void ldm_x4_t(uint32_t* r, uint32_t addr) {
    asm volatile("ldmatrix.sync.aligned.m8n8.x4.trans.shared.b16 {%0,%1,%2,%3}, [%4];\n"
                 : "=r"(r[0]), "=r"(r[1]), "=r"(r[2]), "=r"(r[3]) : "r"(addr));
}

__device__ __forceinline__ void cp16(void* dst, const void* src) {
    asm volatile("cp.async.cg.shared.global [%0], [%1], 16;\n"
                 :: "r"(sptr(dst)), "l"(src) : "memory");
}
__device__ __forceinline__ void cp_commit() {
    asm volatile("cp.async.commit_group;\n" ::: "memory");
}
template <int N>
__device__ __forceinline__ void cp_wait() {
    asm volatile("cp.async.wait_group %0;\n" :: "n"(N) : "memory");
}

__device__ __forceinline__ uint32_t pack_h2(float x, float y) {
    __half2 h = __floats2half2_rn(x, y);
    return *reinterpret_cast<uint32_t*>(&h);
}
__device__ __forceinline__ void store_out(__half* p, float v0, float v1) {
    *reinterpret_cast<__half2*>(p) = __floats2half2_rn(v0, v1);
}
__device__ __forceinline__ void store_out(float* p, float v0, float v1) {
    *reinterpret_cast<float2*>(p) = make_float2(v0, v1);
}

// ---------------------------------------------------------------------------
// fp32 -> fp16 elementwise conversion (vectorized)
// ---------------------------------------------------------------------------
__global__ __launch_bounds__(256)
void cvt_kernel(const float4* __restrict__ in, uint2* __restrict__ out, int n4) {
    int i = blockIdx.x * blockDim.x + threadIdx.x;
    if (i < n4) {
        float4 v = in[i];
        __half2 a = __floats2half2_rn(v.x, v.y);
        __half2 b = __floats2half2_rn(v.z, v.w);
        out[i] = make_uint2(*(uint32_t*)&a, *(uint32_t*)&b);
    }
}

// ---------------------------------------------------------------------------
// fp16 GEMM: C[M,N] = A @ W + bias.  128x128 tile, ktile 32, 8 warps,
// cp.async double buffer, ldmatrix fragment loads.
// ---------------------------------------------------------------------------
template <typename OT>
__global__ __launch_bounds__(256)
void gemm16(const __half* __restrict__ Ah, const __half* __restrict__ Wh,
            const float* __restrict__ bias, OT* __restrict__ C,
            int M, int N, int K) {
    __shared__ alignas(16) __half As[2][128][40];   // [m][k]
    __shared__ alignas(16) __half Bs[2][32][136];   // [k][n]

    const int tid = threadIdx.x;
    const int warp = tid >> 5, lane = tid & 31;
    const int g = lane >> 2, t = lane & 3;
    const int bm = blockIdx.y * 128, bn = blockIdx.x * 128;
    const int wm = (warp >> 1) * 32, wn = (warp & 1) * 64;
    const int lrow = lane & 15, lcol = (lane >> 4) * 8;

    float acc[2][8][4];
#pragma unroll
    for (int a = 0; a < 2; a++)
#pragma unroll
        for (int b = 0; b < 8; b++)
#pragma unroll
            for (int c = 0; c < 4; c++) acc[a][b][c] = 0.f;

    const int NT = K >> 5;

    auto load_tile = [&](int kt, int buf) {
        const int k0 = kt * 32;
        // A tile: 128 rows x 32 halves = 512 x 16B chunks
#pragma unroll
        for (int j = 0; j < 2; j++) {
            int idx = tid + j * 256;
            int r = idx >> 2, c = idx & 3;
            cp16(&As[buf][r][c * 8], Ah + (size_t)(bm + r) * K + k0 + c * 8);
        }
        // B tile: 32 rows x 128 halves = 512 x 16B chunks
#pragma unroll
        for (int j = 0; j < 2; j++) {
            int idx = tid + j * 256;
            int r = idx >> 4, c = idx & 15;
            cp16(&Bs[buf][r][c * 8], Wh + (size_t)(k0 + r) * N + bn + c * 8);
        }
    };

    load_tile(0, 0);
    cp_commit();

    int buf = 0;
    for (int kt = 0; kt < NT; kt++) {
        if (kt + 1 < NT) {
            load_tile(kt + 1, buf ^ 1);
            cp_commit();
            cp_wait<1>();
        } else {
            cp_wait<0>();
        }
        __syncthreads();

#pragma unroll
        for (int ks = 0; ks < 2; ks++) {
            uint32_t af[2][4], bf[8][2];
#pragma unroll
            for (int mi = 0; mi < 2; mi++)
                ldm_x4(af[mi], sptr(&As[buf][wm + mi * 16 + lrow][ks * 16 + lcol]));
#pragma unroll
            for (int p = 0; p < 4; p++) {
                uint32_t tmp[4];
                ldm_x4_t(tmp, sptr(&Bs[buf][ks * 16 + lrow][wn + p * 16 + lcol]));
                bf[2 * p][0] = tmp[0]; bf[2 * p][1] = tmp[1];
                bf[2 * p + 1][0] = tmp[2]; bf[2 * p + 1][1] = tmp[3];
            }
#pragma unroll
            for (int mi = 0; mi < 2; mi++)
#pragma unroll
                for (int ni = 0; ni < 8; ni++)
                    mma16816(acc[mi][ni], af[mi], bf[ni]);
        }
        __syncthreads();
        buf ^= 1;
    }

#pragma unroll
    for (int mi = 0; mi < 2; mi++) {
        int r0 = bm + wm + mi * 16 + g;
#pragma unroll
        for (int ni = 0; ni < 8; ni++) {
            int cc = bn + wn + ni * 8 + t * 2;
            float b0 = bias[cc], b1 = bias[cc + 1];
            store_out(&C[(size_t)r0 * N + cc], acc[mi][ni][0] + b0, acc[mi][ni][1] + b1);
            store_out(&C[(size_t)(r0 + 8) * N + cc], acc[mi][ni][2] + b0, acc[mi][ni][3] + b1);
        }
    }
}

// ---------------------------------------------------------------------------
// Flash attention. Block = (b, h, 128-row q tile), 8 warps x 16 rows.
// KV tiles of 64 keys, cp.async double buffered, ldmatrix frags,
// V via ldmatrix.trans (no transposed store).
// ---------------------------------------------------------------------------
__global__ __launch_bounds__(256)
void attn_kernel(const __half* __restrict__ Qp, const __half* __restrict__ Kp,
                 const __half* __restrict__ Vp, __half* __restrict__ Op) {
    __shared__ alignas(16) __half Ks[2][64][72];
    __shared__ alignas(16) __half Vs[2][64][72];

    const int b = blockIdx.z, h = blockIdx.y, qt = blockIdx.x;
    const int kh = h >> 2;
    const int tid = threadIdx.x;
    const int warp = tid >> 5, lane = tid & 31;
    const int g = lane >> 2, t = lane & 3;
    const int lrow = lane & 15, lcol = (lane >> 4) * 8;

    // ---- load Q tile (128 x 64) into Ks overlay, extract frags ----
    __half (*Qs)[72] = reinterpret_cast<__half (*)[72]>(&Ks[0][0][0]);
    const __half* qbase = Qp + (size_t)(b * SS + qt * 128) * DIMS + h * HD;
    // 128 rows x 64 halves = 1024 x 16B chunks
#pragma unroll
    for (int j = 0; j < 4; j++) {
        int idx = tid + j * 256;
        int r = idx >> 3, c = idx & 7;
        cp16(&Qs[r][c * 8], qbase + (size_t)r * DIMS + c * 8);
    }
    cp_commit();
    cp_wait<0>();
    __syncthreads();

    uint32_t qf[4][4];
#pragma unroll
    for (int kk = 0; kk < 4; kk++)
        ldm_x4(qf[kk], sptr(&Qs[warp * 16 + lrow][kk * 16 + lcol]));
    __syncthreads();

    float o[8][4];
#pragma unroll
    for (int j = 0; j < 8; j++)
#pragma unroll
        for (int p = 0; p < 4; p++) o[j][p] = 0.f;
    float m0 = -1e30f, m1 = -1e30f, l0 = 0.f, l1 = 0.f;

    const __half* kbase = Kp + (size_t)(b * SS) * KV_DIM + kh * HD;
    const __half* vbase = Vp + (size_t)(b * SS) * KV_DIM + kh * HD;

    auto load_kv = [&](int kt, int buf) {
        // 64 rows x 64 halves = 512 x 16B chunks per matrix
#pragma unroll
        for (int j = 0; j < 2; j++) {
            int idx = tid + j * 256;
            int r = idx >> 3, c = idx & 7;
            cp16(&Ks[buf][r][c * 8], kbase + (size_t)(kt * 64 + r) * KV_DIM + c * 8);
            cp16(&Vs[buf][r][c * 8], vbase + (size_t)(kt * 64 + r) * KV_DIM + c * 8);
        }
    };

    load_kv(0, 0);
    cp_commit();

    int buf = 0;
    for (int kt = 0; kt < 32; kt++) {
        if (kt + 1 < 32) {
            load_kv(kt + 1, buf ^ 1);
            cp_commit();
            cp_wait<1>();
        } else {
            cp_wait<0>();
        }
        __syncthreads();

        // ---- scores S = Q @ K^T (16 x 64 per warp) ----
        float sc[8][4];
#pragma unroll
        for (int j = 0; j < 8; j++)
#pragma unroll
            for (int p = 0; p < 4; p++) sc[j][p] = 0.f;

#pragma unroll
        for (int kk = 0; kk < 4; kk++) {
            uint32_t kf[8][2];
#pragma unroll
            for (int p = 0; p < 4; p++) {
                uint32_t tmp[4];
                ldm_x4(tmp, sptr(&Ks[buf][p * 16 + lrow][kk * 16 + lcol]));
                kf[2 * p][0] = tmp[0]; kf[2 * p + 1][0] = tmp[1];
                kf[2 * p][1] = tmp[2]; kf[2 * p + 1][1] = tmp[3];
            }
#pragma unroll
            for (int ni = 0; ni < 8; ni++)
                mma16816(sc[ni], qf[kk], kf[ni]);
        }

        // ---- online softmax (rows g, g+8 of this warp's 16) ----
        float mx0 = -1e30f, mx1 = -1e30f;
#pragma unroll
        for (int j = 0; j < 8; j++) {
            mx0 = fmaxf(mx0, fmaxf(sc[j][0], sc[j][1]));
            mx1 = fmaxf(mx1, fmaxf(sc[j][2], sc[j][3]));
        }
        mx0 = fmaxf(mx0, __shfl_xor_sync(0xffffffffu, mx0, 1));
        mx0 = fmaxf(mx0, __shfl_xor_sync(0xffffffffu, mx0, 2));
        mx1 = fmaxf(mx1, __shfl_xor_sync(0xffffffffu, mx1, 1));
        mx1 = fmaxf(mx1, __shfl_xor_sync(0xffffffffu, mx1, 2));

        float nm0 = fmaxf(m0, mx0 * SM_SCALE);
        float nm1 = fmaxf(m1, mx1 * SM_SCALE);
        float f0 = __expf(m0 - nm0), f1 = __expf(m1 - nm1);
        m0 = nm0; m1 = nm1;

        float rs0 = 0.f, rs1 = 0.f;
#pragma unroll
        for (int j = 0; j < 8; j++) {
            sc[j][0] = __expf(sc[j][0] * SM_SCALE - nm0); rs0 += sc[j][0];
            sc[j][1] = __expf(sc[j][1] * SM_SCALE - nm0); rs0 += sc[j][1];
            sc[j][2] = __expf(sc[j][2] * SM_SCALE - nm1); rs1 += sc[j][2];
            sc[j][3] = __expf(sc[j][3] * SM_SCALE - nm1); rs1 += sc[j][3];
        }
        l0 = l0 * f0 + rs0;
        l1 = l1 * f1 + rs1;
#pragma unroll
        for (int j = 0; j < 8; j++) {
            o[j][0] *= f0; o[j][1] *= f0;
            o[j][2] *= f1; o[j][3] *= f1;
        }

        // ---- O += P @ V ----
#pragma unroll
        for (int t2 = 0; t2 < 4; t2++) {
            uint32_t pf[4];
            pf[0] = pack_h2(sc[2 * t2][0],     sc[2 * t2][1]);
            pf[1] = pack_h2(sc[2 * t2][2],     sc[2 * t2][3]);
            pf[2] = pack_h2(sc[2 * t2 + 1][0], sc[2 * t2 + 1][1]);
            pf[3] = pack_h2(sc[2 * t2 + 1][2], sc[2 * t2 + 1][3]);

            uint32_t vf[8][2];
#pragma unroll
            for (int p = 0; p < 4; p++) {
                uint32_t tmp[4];
                ldm_x4_t(tmp, sptr(&Vs[buf][t2 * 16 + lrow][p * 16 + lcol]));
                vf[2 * p][0] = tmp[0]; vf[2 * p][1] = tmp[1];
                vf[2 * p + 1][0] = tmp[2]; vf[2 * p + 1][1] = tmp[3];
            }
#pragma unroll
            for (int dj = 0; dj < 8; dj++)
                mma16816(o[dj], pf, vf[dj]);
        }
        __syncthreads();
        buf ^= 1;
    }

    // ---- finalize ----
    l0 += __shfl_xor_sync(0xffffffffu, l0, 1);
    l0 += __shfl_xor_sync(0xffffffffu, l0, 2);
    l1 += __shfl_xor_sync(0xffffffffu, l1, 1);
    l1 += __shfl_xor_sync(0xffffffffu, l1, 2);
    float inv0 = 1.f / l0, inv1 = 1.f / l1;

    int q0 = qt * 128 + warp * 16 + g;
#pragma unroll
    for (int j = 0; j < 8; j++) {
        int cc = h * HD + j * 8 + t * 2;
        *(__half2*)&Op[(size_t)(b * SS + q0) * DIMS + cc] =
            __floats2half2_rn(o[j][0] * inv0, o[j][1] * inv0);
        *(__half2*)&Op[(size_t)(b * SS + q0 + 8) * DIMS + cc] =
            __floats2half2_rn(o[j][2] * inv1, o[j][3] * inv1);
    }
}

// ---------------------------------------------------------------------------

static inline void cvt_launch(const float* in, __half* out, size_t n) {
    int n4 = (int)(n / 4);
    cvt_kernel<<<(n4 + 255) / 256, 256>>>((const float4*)in, (uint2*)out, n4);
}

extern "C" void kernel_launch(void* const* d_in, const int* in_sizes, int n_in,
                              void* d_out, int out_size) {
    const float* q  = (const float*)d_in[0];
    const float* k  = (const float*)d_in[1];
    const float* v  = (const float*)d_in[2];
    const float* Wq = (const float*)d_in[3];
    const float* bq = (const float*)d_in[4];
    const float* Wk = (const float*)d_in[5];
    const float* bk = (const float*)d_in[6];
    const float* Wv = (const float*)d_in[7];
    const float* bv = (const float*)d_in[8];
    const float* Wo = (const float*)d_in[9];
    const float* bo = (const float*)d_in[10];
    float* out = (float*)d_out;

    __half *q16, *k16, *v16, *wq16, *wk16, *wv16, *wo16, *gq, *gk, *gv, *ga;
    cudaGetSymbolAddress((void**)&q16,  g_q16);
    cudaGetSymbolAddress((void**)&k16,  g_k16);
    cudaGetSymbolAddress((void**)&v16,  g_v16);
    cudaGetSymbolAddress((void**)&wq16, g_Wq16);
    cudaGetSymbolAddress((void**)&wk16, g_Wk16);
    cudaGetSymbolAddress((void**)&wv16, g_Wv16);
    cudaGetSymbolAddress((void**)&wo16, g_Wo16);
    cudaGetSymbolAddress((void**)&gq,   g_Q);
    cudaGetSymbolAddress((void**)&gk,   g_K);
    cudaGetSymbolAddress((void**)&gv,   g_V);
    cudaGetSymbolAddress((void**)&ga,   g_A);

    cvt_launch(q,  q16,  (size_t)MROWS * IN_DIM);
    cvt_launch(k,  k16,  (size_t)MROWS * IN_DIM);
    cvt_launch(v,  v16,  (size_t)MROWS * IN_DIM);
    cvt_launch(Wq, wq16, (size_t)IN_DIM * DIMS);
    cvt_launch(Wk, wk16, (size_t)IN_DIM * KV_DIM);
    cvt_launch(Wv, wv16, (size_t)IN_DIM * KV_DIM);
    cvt_launch(Wo, wo16, (size_t)DIMS * IN_DIM);

    gemm16<__half><<<dim3(DIMS / 128, MROWS / 128), 256>>>(
        q16, wq16, bq, gq, MROWS, DIMS, IN_DIM);
    gemm16<__half><<<dim3(KV_DIM / 128, MROWS / 128), 256>>>(
        k16, wk16, bk, gk, MROWS, KV_DIM, IN_DIM);
    gemm16<__half><<<dim3(KV_DIM / 128, MROWS / 128), 256>>>(
        v16, wv16, bv, gv, MROWS, KV_DIM, IN_DIM);

    attn_kernel<<<dim3(SS / 128, QH, BB), 256>>>(gq, gk, gv, ga);

    gemm16<float><<<dim3(DIMS / 128, MROWS / 128), 256>>>(
        ga, wo16, bo, out, MROWS, DIMS, IN_DIM);
}